// round 1
// baseline (speedup 1.0000x reference)
#include <cuda_runtime.h>
#include <math.h>

#define Nn 8192
#define IN_FEAT 128
#define OUTF 64
#define LALPHA 0.2f
#define NEG_BIG (-9e15f)

#define BI 64          // rows per CTA in main kernel
#define BJ 128         // j-chunk size
#define TPB 256
#define PSS 68         // padded stride for p matrix [j][i] in smem (bank-conflict relief)
#define SMEM_BYTES ((BJ*OUTF + BJ*PSS)*4)

// Scratch (device globals — no allocation allowed)
__device__ float g_h[Nn*OUTF];
__device__ float g_si[Nn];
__device__ float g_sj[Nn];
__device__ float g_sjmax;

// ---------------------------------------------------------------------------
// K1: h = features @ W.T   (h[i][f] = sum_k feat[i][k] * W[f][k])
// Block: 256 threads, 32 rows. W transposed into smem once per block.
// ---------------------------------------------------------------------------
__global__ void __launch_bounds__(256) k_h(const float* __restrict__ feat,
                                           const float* __restrict__ W) {
    __shared__ float Wt[IN_FEAT][OUTF];   // Wt[k][f] = W[f][k], 32 KB
    int t = threadIdx.x;

    // Cooperative transposed load of W (64x128 floats = 2048 float4)
#pragma unroll
    for (int w = 0; w < 8; w++) {
        int idx = t + 256 * w;            // 0..2047
        int f   = idx >> 5;               // 32 float4 per W row
        int c4  = idx & 31;
        float4 wv = ((const float4*)W)[idx];
        int k = c4 * 4;
        Wt[k + 0][f] = wv.x;
        Wt[k + 1][f] = wv.y;
        Wt[k + 2][f] = wv.z;
        Wt[k + 3][f] = wv.w;
    }
    __syncthreads();

    int il = t >> 3;                      // 0..31 row within block
    int fo = t & 7;                       // 8 output features per thread
    int i  = blockIdx.x * 32 + il;

    const float4* fr = (const float4*)(feat + (size_t)i * IN_FEAT);

    float acc[8];
#pragma unroll
    for (int c = 0; c < 8; c++) acc[c] = 0.f;

#pragma unroll
    for (int kk = 0; kk < 32; kk++) {
        float4 fv = fr[kk];               // broadcast across lanes (same i per 8 lanes)
#pragma unroll
        for (int c = 0; c < 4; c++) {
            float fc = (c == 0) ? fv.x : (c == 1) ? fv.y : (c == 2) ? fv.z : fv.w;
            int k = kk * 4 + c;
            float4 w0 = *(const float4*)&Wt[k][fo * 8];
            float4 w1 = *(const float4*)&Wt[k][fo * 8 + 4];
            acc[0] += fc * w0.x; acc[1] += fc * w0.y;
            acc[2] += fc * w0.z; acc[3] += fc * w0.w;
            acc[4] += fc * w1.x; acc[5] += fc * w1.y;
            acc[6] += fc * w1.z; acc[7] += fc * w1.w;
        }
    }
    float4 o0 = make_float4(acc[0], acc[1], acc[2], acc[3]);
    float4 o1 = make_float4(acc[4], acc[5], acc[6], acc[7]);
    *(float4*)(g_h + (size_t)i * OUTF + fo * 8)     = o0;
    *(float4*)(g_h + (size_t)i * OUTF + fo * 8 + 4) = o1;
}

// ---------------------------------------------------------------------------
// K2: s_i = h . a[:64], s_j = h . a[64:]
// ---------------------------------------------------------------------------
__global__ void __launch_bounds__(256) k_s(const float* __restrict__ avec) {
    int i = blockIdx.x * blockDim.x + threadIdx.x;
    const float4* hr = (const float4*)(g_h + (size_t)i * OUTF);
    const float4* a1 = (const float4*)avec;
    const float4* a2 = (const float4*)(avec + OUTF);
    float x = 0.f, y = 0.f;
#pragma unroll
    for (int k = 0; k < 16; k++) {
        float4 h4 = hr[k];
        float4 u = a1[k];
        float4 v = a2[k];
        x += h4.x * u.x + h4.y * u.y + h4.z * u.z + h4.w * u.w;
        y += h4.x * v.x + h4.y * v.y + h4.z * v.z + h4.w * v.w;
    }
    g_si[i] = x;
    g_sj[i] = y;
}

// ---------------------------------------------------------------------------
// K3: g_sjmax = max_j s_j  (single block)
// ---------------------------------------------------------------------------
__global__ void __launch_bounds__(256) k_max() {
    __shared__ float sm[256];
    int t = threadIdx.x;
    float m = -1e30f;
    for (int j = t; j < Nn; j += 256) m = fmaxf(m, g_sj[j]);
    sm[t] = m;
    __syncthreads();
    for (int o = 128; o > 0; o >>= 1) {
        if (t < o) sm[t] = fmaxf(sm[t], sm[t + o]);
        __syncthreads();
    }
    if (t == 0) g_sjmax = sm[0];
}

// ---------------------------------------------------------------------------
// K4: fused scores + softmax (fixed upper-bound shift) + P@H + ELU
// Grid: 128 CTAs x 256 threads. CTA owns rows [i0, i0+64).
// ---------------------------------------------------------------------------
__global__ void __launch_bounds__(TPB) k_main(const float* __restrict__ geo,
                                              const float* __restrict__ sem,
                                              float* __restrict__ out) {
    extern __shared__ float smem[];
    float* hs = smem;                 // [BJ][OUTF]  h chunk
    float* ps = smem + BJ * OUTF;     // [BJ][PSS]   p (transposed [j][i])

    __shared__ float sjs[BJ];
    __shared__ float lfin[BI];

    int t  = threadIdx.x;
    int i0 = blockIdx.x * BI;

    // --- score-phase mapping: 4 threads per row ---
    int r = t >> 2;                   // row 0..63
    int q = t & 3;                    // quarter of the j-chunk
    float si_r = g_si[i0 + r];
    float m_r  = fmaxf(0.f, 2.f * (si_r + g_sjmax));   // provable upper bound on row scores
    float l_acc = 0.f;

    // --- gemm-phase mapping: 4x4 register tile ---
    int ip = t >> 4;                  // i-group 0..15  (rows ip*4 .. ip*4+3)
    int fq = t & 15;                  // f-group 0..15  (cols fq*4 .. fq*4+3)

    float acc[4][4];
#pragma unroll
    for (int a = 0; a < 4; a++)
#pragma unroll
        for (int b = 0; b < 4; b++) acc[a][b] = 0.f;

    const float4* gbase = (const float4*)(geo + (size_t)(i0 + r) * Nn);
    const float4* sbase = (const float4*)(sem + (size_t)(i0 + r) * Nn);

    int jr = t >> 4, f4 = t & 15;     // h staging mapping

    for (int jc = 0; jc < Nn; jc += BJ) {
        // Prefetch adjacency tiles for this chunk into registers (16 LDG.128 in flight)
        int jb4 = jc >> 2;
        float4 gv[8], sv[8];
#pragma unroll
        for (int kk = 0; kk < 8; kk++) {
            int jf4 = q + 4 * kk;
            gv[kk] = gbase[jb4 + jf4];
            sv[kk] = sbase[jb4 + jf4];
        }

        __syncthreads();   // previous GEMM done reading hs/ps

        // Stage h chunk + s_j chunk
#pragma unroll
        for (int it = 0; it < 8; it++) {
            int j = jr + 16 * it;
            float4 hv = *(const float4*)(g_h + (size_t)(jc + j) * OUTF + f4 * 4);
            *(float4*)(hs + j * OUTF + f4 * 4) = hv;
        }
        if (t < BJ) sjs[t] = g_sj[jc + t];

        __syncthreads();   // sjs/hs visible

        // Scores -> p = exp(val - m_r), store transposed ps[j][r]
#pragma unroll
        for (int kk = 0; kk < 8; kk++) {
            int j0l = (q + 4 * kk) * 4;
            float4 g4 = gv[kk];
            float4 s4 = sv[kk];
#pragma unroll
            for (int c = 0; c < 4; c++) {
                float g = (c == 0) ? g4.x : (c == 1) ? g4.y : (c == 2) ? g4.z : g4.w;
                float s = (c == 0) ? s4.x : (c == 1) ? s4.y : (c == 2) ? s4.z : s4.w;
                int j = j0l + c;
                float cmb = g + s;
                float x = si_r + sjs[j];
                x = (x > 0.f) ? x : LALPHA * x;
                float e = x * cmb;
                float val = (cmb > 0.f) ? e : NEG_BIG;
                float p = __expf(val - m_r);    // underflows to exact 0 for masked entries
                ps[(size_t)j * PSS + r] = p;
                l_acc += p;
            }
        }

        __syncthreads();   // ps ready

        // GEMM: acc[4][4] += P[64,128] @ H[128,64] register-tiled
        const float4* pp = (const float4*)(ps + ip * 4);
        const float4* hp = (const float4*)(hs + fq * 4);
#pragma unroll 8
        for (int k = 0; k < BJ; k++) {
            float4 pv = pp[k * (PSS / 4)];
            float4 hv = hp[k * (OUTF / 4)];
            float pa[4] = {pv.x, pv.y, pv.z, pv.w};
            float hb[4] = {hv.x, hv.y, hv.z, hv.w};
#pragma unroll
            for (int a = 0; a < 4; a++)
#pragma unroll
                for (int b = 0; b < 4; b++)
                    acc[a][b] += pa[a] * hb[b];
        }
    }

    // Reduce l across the 4 threads of each row (contiguous lanes, width-4 shuffle)
    l_acc += __shfl_down_sync(0xffffffffu, l_acc, 2, 4);
    l_acc += __shfl_down_sync(0xffffffffu, l_acc, 1, 4);
    if (q == 0) lfin[r] = l_acc;
    __syncthreads();

    // Epilogue: out = elu(acc / l)
#pragma unroll
    for (int a = 0; a < 4; a++) {
        int i = ip * 4 + a;
        float inv = 1.f / lfin[i];
        float4 o;
        float v;
        v = acc[a][0] * inv; o.x = (v > 0.f) ? v : expm1f(v);
        v = acc[a][1] * inv; o.y = (v > 0.f) ? v : expm1f(v);
        v = acc[a][2] * inv; o.z = (v > 0.f) ? v : expm1f(v);
        v = acc[a][3] * inv; o.w = (v > 0.f) ? v : expm1f(v);
        *(float4*)(out + (size_t)(i0 + i) * OUTF + fq * 4) = o;
    }
}

// ---------------------------------------------------------------------------
extern "C" void kernel_launch(void* const* d_in, const int* in_sizes, int n_in,
                              void* d_out, int out_size) {
    const float* geo  = (const float*)d_in[0];
    const float* sem  = (const float*)d_in[1];
    const float* feat = (const float*)d_in[2];
    const float* W    = (const float*)d_in[3];
    const float* avec = (const float*)d_in[4];
    float* out = (float*)d_out;

    k_h<<<Nn / 32, 256>>>(feat, W);
    k_s<<<Nn / 256, 256>>>(avec);
    k_max<<<1, 256>>>();

    cudaFuncSetAttribute(k_main, cudaFuncAttributeMaxDynamicSharedMemorySize, SMEM_BYTES);
    k_main<<<Nn / BI, TPB, SMEM_BYTES>>>(geo, sem, out);
}

// round 2
// speedup vs baseline: 2.0180x; 2.0180x over previous
#include <cuda_runtime.h>
#include <math.h>
#include <stdint.h>

#define Nn 8192
#define IN_FEAT 128
#define OUTF 64
#define LALPHA 0.2f
#define NEG_BIG (-9e15f)

#define BI 64          // rows per CTA
#define BJ 128         // j-chunk
#define TPB 256
#define HST 72         // hs stride (floats); 72 % 32 == 8 -> B-frag LDS conflict-free
#define PST 132        // ps stride (floats); 132 % 32 == 4 -> A-frag LDS conflict-free
#define SMEM_BYTES ((2*BJ*HST + BI*PST)*4)

// Scratch (device globals — no allocation allowed)
__device__ float g_h[Nn*OUTF];
__device__ float g_si[Nn];
__device__ float g_sj[Nn];
__device__ float g_sjmax;

__device__ __forceinline__ uint32_t f2tf(float x) {
    uint32_t r;
    asm("cvt.rna.tf32.f32 %0, %1;" : "=r"(r) : "f"(x));
    return r;
}

__device__ __forceinline__ void mma_tf32(float* c,
                                         uint32_t a0, uint32_t a1, uint32_t a2, uint32_t a3,
                                         uint32_t b0, uint32_t b1) {
    asm volatile(
        "mma.sync.aligned.m16n8k8.row.col.f32.tf32.tf32.f32 "
        "{%0,%1,%2,%3}, {%4,%5,%6,%7}, {%8,%9}, {%0,%1,%2,%3};"
        : "+f"(c[0]), "+f"(c[1]), "+f"(c[2]), "+f"(c[3])
        : "r"(a0), "r"(a1), "r"(a2), "r"(a3), "r"(b0), "r"(b1));
}

// ---------------------------------------------------------------------------
// K1: h = features @ W.T
// ---------------------------------------------------------------------------
__global__ void __launch_bounds__(256) k_h(const float* __restrict__ feat,
                                           const float* __restrict__ W) {
    __shared__ float Wt[IN_FEAT][OUTF];
    int t = threadIdx.x;
#pragma unroll
    for (int w = 0; w < 8; w++) {
        int idx = t + 256 * w;
        int f   = idx >> 5;
        int c4  = idx & 31;
        float4 wv = ((const float4*)W)[idx];
        int k = c4 * 4;
        Wt[k + 0][f] = wv.x;
        Wt[k + 1][f] = wv.y;
        Wt[k + 2][f] = wv.z;
        Wt[k + 3][f] = wv.w;
    }
    __syncthreads();

    int il = t >> 3;
    int fo = t & 7;
    int i  = blockIdx.x * 32 + il;
    const float4* fr = (const float4*)(feat + (size_t)i * IN_FEAT);

    float acc[8];
#pragma unroll
    for (int c = 0; c < 8; c++) acc[c] = 0.f;

#pragma unroll
    for (int kk = 0; kk < 32; kk++) {
        float4 fv = fr[kk];
#pragma unroll
        for (int c = 0; c < 4; c++) {
            float fc = (c == 0) ? fv.x : (c == 1) ? fv.y : (c == 2) ? fv.z : fv.w;
            int k = kk * 4 + c;
            float4 w0 = *(const float4*)&Wt[k][fo * 8];
            float4 w1 = *(const float4*)&Wt[k][fo * 8 + 4];
            acc[0] += fc * w0.x; acc[1] += fc * w0.y;
            acc[2] += fc * w0.z; acc[3] += fc * w0.w;
            acc[4] += fc * w1.x; acc[5] += fc * w1.y;
            acc[6] += fc * w1.z; acc[7] += fc * w1.w;
        }
    }
    *(float4*)(g_h + (size_t)i * OUTF + fo * 8)     = make_float4(acc[0], acc[1], acc[2], acc[3]);
    *(float4*)(g_h + (size_t)i * OUTF + fo * 8 + 4) = make_float4(acc[4], acc[5], acc[6], acc[7]);
}

// ---------------------------------------------------------------------------
// K2: s_i, s_j
// ---------------------------------------------------------------------------
__global__ void __launch_bounds__(256) k_s(const float* __restrict__ avec) {
    int i = blockIdx.x * blockDim.x + threadIdx.x;
    const float4* hr = (const float4*)(g_h + (size_t)i * OUTF);
    const float4* a1 = (const float4*)avec;
    const float4* a2 = (const float4*)(avec + OUTF);
    float x = 0.f, y = 0.f;
#pragma unroll
    for (int k = 0; k < 16; k++) {
        float4 h4 = hr[k];
        float4 u = a1[k];
        float4 v = a2[k];
        x += h4.x * u.x + h4.y * u.y + h4.z * u.z + h4.w * u.w;
        y += h4.x * v.x + h4.y * v.y + h4.z * v.z + h4.w * v.w;
    }
    g_si[i] = x;
    g_sj[i] = y;
}

// ---------------------------------------------------------------------------
// K3: g_sjmax = max_j s_j
// ---------------------------------------------------------------------------
__global__ void __launch_bounds__(256) k_max() {
    __shared__ float sm[256];
    int t = threadIdx.x;
    float m = -1e30f;
    for (int j = t; j < Nn; j += 256) m = fmaxf(m, g_sj[j]);
    sm[t] = m;
    __syncthreads();
    for (int o = 128; o > 0; o >>= 1) {
        if (t < o) sm[t] = fmaxf(sm[t], sm[t + o]);
        __syncthreads();
    }
    if (t == 0) g_sjmax = sm[0];
}

// ---------------------------------------------------------------------------
// K4: fused scores + single-pass softmax + tf32 tensor-core P@H + ELU
// Grid: 128 CTAs x 256 threads. CTA owns rows [i0, i0+64).
// ---------------------------------------------------------------------------
__global__ void __launch_bounds__(TPB) k_main(const float* __restrict__ geo,
                                              const float* __restrict__ sem,
                                              float* __restrict__ out) {
    extern __shared__ float smem[];
    float* hs0 = smem;                      // [BJ][HST] tf32 h chunk, buffer 0
    float* hs1 = smem + BJ * HST;           // buffer 1
    float* ps  = smem + 2 * BJ * HST;       // [BI][PST] tf32 p tile

    __shared__ float sjs[BJ];
    __shared__ float lfin[BI];

    int t    = threadIdx.x;
    int i0   = blockIdx.x * BI;
    int lane = t & 31;
    int warp = t >> 5;

    // ---- score-phase mapping: 4 threads per row ----
    int r = t >> 2;
    int q = t & 3;
    float si_r  = g_si[i0 + r];
    float m_r   = fmaxf(0.f, 2.f * (si_r + g_sjmax));
    float l_acc = 0.f;
    const float4* gbase = (const float4*)(geo + (size_t)(i0 + r) * Nn);
    const float4* sbase = (const float4*)(sem + (size_t)(i0 + r) * Nn);

    // ---- staging mapping ----
    int jr = t >> 4, f4 = t & 15;

    // ---- gemm mapping: 8 warps = 4(m) x 2(n); warp tile m16 x n32 ----
    int wm = warp & 3, wn = warp >> 2;
    int m0 = wm * 16, n0 = wn * 32;
    int ar = lane >> 2, ac = lane & 3;       // A-frag row/col within tile
    int bk = lane & 3,  bn = lane >> 2;      // B-frag k/n within tile

    float acc[4][4];
#pragma unroll
    for (int a = 0; a < 4; a++)
#pragma unroll
        for (int b = 0; b < 4; b++) acc[a][b] = 0.f;

    // prefetch adjacency chunk 0
    float4 gv[8], sv[8];
#pragma unroll
    for (int kk = 0; kk < 8; kk++) {
        gv[kk] = gbase[q + 4 * kk];
        sv[kk] = sbase[q + 4 * kk];
    }

    int buf = 0;
    for (int jc = 0; jc < Nn; jc += BJ, buf ^= 1) {
        float* hs = buf ? hs1 : hs0;

        // ---- stage h chunk (convert to tf32) ----
#pragma unroll
        for (int it = 0; it < 8; it++) {
            int j = jr + 16 * it;
            float4 hv = *(const float4*)(g_h + (size_t)(jc + j) * OUTF + f4 * 4);
            uint32_t* d = (uint32_t*)(hs + j * HST + f4 * 4);
            uint4 o;
            o.x = f2tf(hv.x); o.y = f2tf(hv.y); o.z = f2tf(hv.z); o.w = f2tf(hv.w);
            *(uint4*)d = o;
        }
        if (t < BJ) sjs[t] = g_sj[jc + t];

        __syncthreads();   // hs[buf] staged; prev GEMM done reading ps

        // ---- scores -> p = exp(val - m_r), tf32, row-major ps[i][j] ----
#pragma unroll
        for (int kk = 0; kk < 8; kk++) {
            int j0l = (q + 4 * kk) * 4;
            float4 g4 = gv[kk];
            float4 s4 = sv[kk];
            uint4 po;
            uint32_t* pd = (uint32_t*)&po;
#pragma unroll
            for (int c = 0; c < 4; c++) {
                float g = (c == 0) ? g4.x : (c == 1) ? g4.y : (c == 2) ? g4.z : g4.w;
                float s = (c == 0) ? s4.x : (c == 1) ? s4.y : (c == 2) ? s4.z : s4.w;
                float cmb = g + s;
                float x = si_r + sjs[j0l + c];
                x = (x > 0.f) ? x : LALPHA * x;
                float e = x * cmb;
                float val = (cmb > 0.f) ? e : NEG_BIG;
                float p = __expf(val - m_r);
                l_acc += p;
                pd[c] = f2tf(p);
            }
            *(uint4*)(ps + r * PST + j0l) = po;
        }

        // ---- prefetch next adjacency chunk (hidden under GEMM) ----
        int jn = jc + BJ;
        if (jn >= Nn) jn = 0;
        int jb4 = jn >> 2;
#pragma unroll
        for (int kk = 0; kk < 8; kk++) {
            gv[kk] = gbase[jb4 + q + 4 * kk];
            sv[kk] = sbase[jb4 + q + 4 * kk];
        }

        __syncthreads();   // ps ready

        // ---- tensor-core GEMM: acc += P[64,128] @ H[128,64] ----
        const float* psA = ps + (m0 + ar) * PST + ac;
        const float* hsB = hs + bk * HST + n0 + bn;
#pragma unroll
        for (int ks = 0; ks < 16; ks++) {
            int k0 = ks * 8;
            uint32_t a0 = __float_as_uint(psA[k0]);
            uint32_t a1 = __float_as_uint(psA[8 * PST + k0]);
            uint32_t a2 = __float_as_uint(psA[k0 + 4]);
            uint32_t a3 = __float_as_uint(psA[8 * PST + k0 + 4]);
#pragma unroll
            for (int nt = 0; nt < 4; nt++) {
                uint32_t b0 = __float_as_uint(hsB[k0 * HST + nt * 8]);
                uint32_t b1 = __float_as_uint(hsB[(k0 + 4) * HST + nt * 8]);
                mma_tf32(acc[nt], a0, a1, a2, a3, b0, b1);
            }
        }
    }

    // ---- reduce l across the 4 threads of each row ----
    l_acc += __shfl_down_sync(0xffffffffu, l_acc, 2, 4);
    l_acc += __shfl_down_sync(0xffffffffu, l_acc, 1, 4);
    if (q == 0) lfin[r] = l_acc;
    __syncthreads();

    // ---- epilogue: out = elu(acc / l) ----
    int row0 = m0 + (lane >> 2);
    int col0 = 2 * (lane & 3);
    float inv0 = 1.f / lfin[row0];
    float inv1 = 1.f / lfin[row0 + 8];
#pragma unroll
    for (int nt = 0; nt < 4; nt++) {
        int col = n0 + nt * 8 + col0;
        float v0 = acc[nt][0] * inv0;
        float v1 = acc[nt][1] * inv0;
        float v2 = acc[nt][2] * inv1;
        float v3 = acc[nt][3] * inv1;
        float2 o01, o23;
        o01.x = (v0 > 0.f) ? v0 : expm1f(v0);
        o01.y = (v1 > 0.f) ? v1 : expm1f(v1);
        o23.x = (v2 > 0.f) ? v2 : expm1f(v2);
        o23.y = (v3 > 0.f) ? v3 : expm1f(v3);
        *(float2*)(out + (size_t)(i0 + row0) * OUTF + col)     = o01;
        *(float2*)(out + (size_t)(i0 + row0 + 8) * OUTF + col) = o23;
    }
}

// ---------------------------------------------------------------------------
extern "C" void kernel_launch(void* const* d_in, const int* in_sizes, int n_in,
                              void* d_out, int out_size) {
    const float* geo  = (const float*)d_in[0];
    const float* sem  = (const float*)d_in[1];
    const float* feat = (const float*)d_in[2];
    const float* W    = (const float*)d_in[3];
    const float* avec = (const float*)d_in[4];
    float* out = (float*)d_out;

    k_h<<<Nn / 32, 256>>>(feat, W);
    k_s<<<Nn / 256, 256>>>(avec);
    k_max<<<1, 256>>>();

    cudaFuncSetAttribute(k_main, cudaFuncAttributeMaxDynamicSharedMemorySize, SMEM_BYTES);
    k_main<<<Nn / BI, TPB, SMEM_BYTES>>>(geo, sem, out);
}

// round 3
// speedup vs baseline: 2.6906x; 1.3333x over previous
#include <cuda_runtime.h>
#include <math.h>
#include <stdint.h>

#define Nn 8192
#define IN_FEAT 128
#define OUTF 64
#define LALPHA 0.2f
#define NEG_BIG (-9e15f)

#define BI 32          // rows per CTA
#define BJ 128         // j-chunk
#define TPB 256
#define HST 72         // hs stride (floats); 72 % 32 == 8 -> B-frag LDS conflict-free
#define PST 132        // ps stride (floats); 132 % 32 == 4 -> A-frag LDS conflict-free
#define SMEM_BYTES ((2*BJ*HST + BI*PST)*4)

// Scratch (device globals — no allocation allowed)
__device__ float g_h[Nn*OUTF];
__device__ float g_si[Nn];
__device__ float g_sj[Nn];
__device__ unsigned g_sjmax_enc;   // order-preserving unsigned encoding; zero-init == -inf

__device__ __forceinline__ uint32_t f2tf(float x) {
    uint32_t r;
    asm("cvt.rna.tf32.f32 %0, %1;" : "=r"(r) : "f"(x));
    return r;
}

__device__ __forceinline__ unsigned enc_f(float x) {
    unsigned u = __float_as_uint(x);
    return (u & 0x80000000u) ? ~u : (u | 0x80000000u);
}
__device__ __forceinline__ float dec_f(unsigned u) {
    return __uint_as_float((u & 0x80000000u) ? (u & 0x7FFFFFFFu) : ~u);
}

__device__ __forceinline__ void mma_tf32(float* c,
                                         uint32_t a0, uint32_t a1, uint32_t a2, uint32_t a3,
                                         uint32_t b0, uint32_t b1) {
    asm volatile(
        "mma.sync.aligned.m16n8k8.row.col.f32.tf32.tf32.f32 "
        "{%0,%1,%2,%3}, {%4,%5,%6,%7}, {%8,%9}, {%0,%1,%2,%3};"
        : "+f"(c[0]), "+f"(c[1]), "+f"(c[2]), "+f"(c[3])
        : "r"(a0), "r"(a1), "r"(a2), "r"(a3), "r"(b0), "r"(b1));
}

// ---------------------------------------------------------------------------
// K1: h = features @ W.T, fused with s_i/s_j and global max(s_j)
// ---------------------------------------------------------------------------
__global__ void __launch_bounds__(256) k_h(const float* __restrict__ feat,
                                           const float* __restrict__ W,
                                           const float* __restrict__ avec) {
    __shared__ float Wt[IN_FEAT][OUTF];
    __shared__ float sjred[32];
    int t = threadIdx.x;
#pragma unroll
    for (int w = 0; w < 8; w++) {
        int idx = t + 256 * w;
        int f   = idx >> 5;
        int c4  = idx & 31;
        float4 wv = ((const float4*)W)[idx];
        int k = c4 * 4;
        Wt[k + 0][f] = wv.x;
        Wt[k + 1][f] = wv.y;
        Wt[k + 2][f] = wv.z;
        Wt[k + 3][f] = wv.w;
    }
    __syncthreads();

    int il = t >> 3;
    int fo = t & 7;
    int i  = blockIdx.x * 32 + il;
    const float4* fr = (const float4*)(feat + (size_t)i * IN_FEAT);

    float acc[8];
#pragma unroll
    for (int c = 0; c < 8; c++) acc[c] = 0.f;

#pragma unroll
    for (int kk = 0; kk < 32; kk++) {
        float4 fv = fr[kk];
#pragma unroll
        for (int c = 0; c < 4; c++) {
            float fc = (c == 0) ? fv.x : (c == 1) ? fv.y : (c == 2) ? fv.z : fv.w;
            int k = kk * 4 + c;
            float4 w0 = *(const float4*)&Wt[k][fo * 8];
            float4 w1 = *(const float4*)&Wt[k][fo * 8 + 4];
            acc[0] += fc * w0.x; acc[1] += fc * w0.y;
            acc[2] += fc * w0.z; acc[3] += fc * w0.w;
            acc[4] += fc * w1.x; acc[5] += fc * w1.y;
            acc[6] += fc * w1.z; acc[7] += fc * w1.w;
        }
    }
    *(float4*)(g_h + (size_t)i * OUTF + fo * 8)     = make_float4(acc[0], acc[1], acc[2], acc[3]);
    *(float4*)(g_h + (size_t)i * OUTF + fo * 8 + 4) = make_float4(acc[4], acc[5], acc[6], acc[7]);

    // fused: s_i = h.a[:64], s_j = h.a[64:]
    float sx = 0.f, sy = 0.f;
#pragma unroll
    for (int c = 0; c < 8; c++) {
        sx += acc[c] * avec[fo * 8 + c];
        sy += acc[c] * avec[OUTF + fo * 8 + c];
    }
#pragma unroll
    for (int o = 4; o > 0; o >>= 1) {
        sx += __shfl_down_sync(0xffffffffu, sx, o, 8);
        sy += __shfl_down_sync(0xffffffffu, sy, o, 8);
    }
    if (fo == 0) {
        g_si[i] = sx;
        g_sj[i] = sy;
        sjred[il] = sy;
    }
    __syncthreads();
    if (t == 0) {
        float m = sjred[0];
#pragma unroll
        for (int c = 1; c < 32; c++) m = fmaxf(m, sjred[c]);
        atomicMax(&g_sjmax_enc, enc_f(m));   // idempotent: same inputs every replay
    }
}

// ---------------------------------------------------------------------------
// K2: fused scores + single-pass softmax + tf32 tensor-core P@H + ELU
// Grid: 256 CTAs x 256 threads, 2 CTAs/SM. CTA owns rows [i0, i0+32).
// ---------------------------------------------------------------------------
__global__ void __launch_bounds__(TPB, 2) k_main(const float* __restrict__ geo,
                                                 const float* __restrict__ sem,
                                                 float* __restrict__ out) {
    extern __shared__ float smem[];
    float* hs0 = smem;                      // [BJ][HST] tf32 h chunk, buffer 0
    float* hs1 = smem + BJ * HST;           // buffer 1
    float* ps  = smem + 2 * BJ * HST;       // [BI][PST] tf32 p tile

    __shared__ float sjs[BJ];
    __shared__ float lfin[BI];

    int t    = threadIdx.x;
    int i0   = blockIdx.x * BI;
    int lane = t & 31;
    int warp = t >> 5;

    // ---- score-phase mapping: 8 threads per row ----
    int r = t >> 3;                         // row 0..31
    int q = t & 7;                          // eighth of the j-chunk
    float si_r  = g_si[i0 + r];
    float m_r   = fmaxf(0.f, 2.f * (si_r + dec_f(g_sjmax_enc)));
    float l_acc = 0.f;
    const float4* gbase = (const float4*)(geo + (size_t)(i0 + r) * Nn);
    const float4* sbase = (const float4*)(sem + (size_t)(i0 + r) * Nn);

    // ---- staging mapping ----
    int jr = t >> 4, f4 = t & 15;

    // ---- gemm mapping: 8 warps = 2(m) x 4(n); warp tile m16 x n16 ----
    int wm = warp & 1, wn = warp >> 1;
    int m0 = wm * 16, n0 = wn * 16;
    int ar = lane >> 2, ac = lane & 3;       // A-frag row/col
    int bk = lane & 3,  bn = lane >> 2;      // B-frag k/n

    float acc[2][4];
#pragma unroll
    for (int a = 0; a < 2; a++)
#pragma unroll
        for (int b = 0; b < 4; b++) acc[a][b] = 0.f;

    // prefetch adjacency chunk 0 (streaming loads, bypass L1)
    float4 gv[4], sv[4];
#pragma unroll
    for (int kk = 0; kk < 4; kk++) {
        gv[kk] = __ldcs(&gbase[q + 8 * kk]);
        sv[kk] = __ldcs(&sbase[q + 8 * kk]);
    }

    int buf = 0;
    for (int jc = 0; jc < Nn; jc += BJ, buf ^= 1) {
        float* hs = buf ? hs1 : hs0;

        // ---- stage h chunk (convert to tf32) ----
#pragma unroll
        for (int it = 0; it < 8; it++) {
            int j = jr + 16 * it;
            float4 hv = *(const float4*)(g_h + (size_t)(jc + j) * OUTF + f4 * 4);
            uint4 o;
            o.x = f2tf(hv.x); o.y = f2tf(hv.y); o.z = f2tf(hv.z); o.w = f2tf(hv.w);
            *(uint4*)(hs + j * HST + f4 * 4) = o;
        }
        if (t < BJ) sjs[t] = g_sj[jc + t];

        __syncthreads();   // hs[buf] staged; prev GEMM done reading ps

        // ---- scores -> p = exp(val - m_r), tf32, row-major ps[i][j] ----
#pragma unroll
        for (int kk = 0; kk < 4; kk++) {
            int j0l = (q + 8 * kk) * 4;
            float4 g4 = gv[kk];
            float4 s4 = sv[kk];
            uint4 po;
            uint32_t* pd = (uint32_t*)&po;
#pragma unroll
            for (int c = 0; c < 4; c++) {
                float g = (c == 0) ? g4.x : (c == 1) ? g4.y : (c == 2) ? g4.z : g4.w;
                float s = (c == 0) ? s4.x : (c == 1) ? s4.y : (c == 2) ? s4.z : s4.w;
                float cmb = g + s;
                float x = si_r + sjs[j0l + c];
                x = (x > 0.f) ? x : LALPHA * x;
                float e = x * cmb;
                float val = (cmb > 0.f) ? e : NEG_BIG;
                float p = __expf(val - m_r);
                l_acc += p;
                pd[c] = f2tf(p);
            }
            *(uint4*)(ps + r * PST + j0l) = po;
        }

        // ---- prefetch next adjacency chunk (hidden under GEMM) ----
        int jn = jc + BJ;
        if (jn >= Nn) jn = 0;
        int jb4 = jn >> 2;
#pragma unroll
        for (int kk = 0; kk < 4; kk++) {
            gv[kk] = __ldcs(&gbase[jb4 + q + 8 * kk]);
            sv[kk] = __ldcs(&sbase[jb4 + q + 8 * kk]);
        }

        __syncthreads();   // ps ready

        // ---- tensor-core GEMM: acc += P[32,128] @ H[128,64] ----
        const float* psA = ps + (m0 + ar) * PST + ac;
        const float* hsB = hs + bk * HST + n0 + bn;
#pragma unroll
        for (int ks = 0; ks < 16; ks++) {
            int k0 = ks * 8;
            uint32_t a0 = __float_as_uint(psA[k0]);
            uint32_t a1 = __float_as_uint(psA[8 * PST + k0]);
            uint32_t a2 = __float_as_uint(psA[k0 + 4]);
            uint32_t a3 = __float_as_uint(psA[8 * PST + k0 + 4]);
#pragma unroll
            for (int nt = 0; nt < 2; nt++) {
                uint32_t b0 = __float_as_uint(hsB[k0 * HST + nt * 8]);
                uint32_t b1 = __float_as_uint(hsB[(k0 + 4) * HST + nt * 8]);
                mma_tf32(acc[nt], a0, a1, a2, a3, b0, b1);
            }
        }
    }

    // ---- reduce l across the 8 threads of each row ----
#pragma unroll
    for (int o = 4; o > 0; o >>= 1)
        l_acc += __shfl_down_sync(0xffffffffu, l_acc, o, 8);
    if (q == 0) lfin[r] = l_acc;
    __syncthreads();

    // ---- epilogue: out = elu(acc / l) ----
    int row0 = m0 + (lane >> 2);
    int col0 = 2 * (lane & 3);
    float inv0 = 1.f / lfin[row0];
    float inv1 = 1.f / lfin[row0 + 8];
#pragma unroll
    for (int nt = 0; nt < 2; nt++) {
        int col = n0 + nt * 8 + col0;
        float v0 = acc[nt][0] * inv0;
        float v1 = acc[nt][1] * inv0;
        float v2 = acc[nt][2] * inv1;
        float v3 = acc[nt][3] * inv1;
        float2 o01, o23;
        o01.x = (v0 > 0.f) ? v0 : expm1f(v0);
        o01.y = (v1 > 0.f) ? v1 : expm1f(v1);
        o23.x = (v2 > 0.f) ? v2 : expm1f(v2);
        o23.y = (v3 > 0.f) ? v3 : expm1f(v3);
        *(float2*)(out + (size_t)(i0 + row0) * OUTF + col)     = o01;
        *(float2*)(out + (size_t)(i0 + row0 + 8) * OUTF + col) = o23;
    }
}

// ---------------------------------------------------------------------------
extern "C" void kernel_launch(void* const* d_in, const int* in_sizes, int n_in,
                              void* d_out, int out_size) {
    const float* geo  = (const float*)d_in[0];
    const float* sem  = (const float*)d_in[1];
    const float* feat = (const float*)d_in[2];
    const float* W    = (const float*)d_in[3];
    const float* avec = (const float*)d_in[4];
    float* out = (float*)d_out;

    k_h<<<Nn / 32, 256>>>(feat, W, avec);

    cudaFuncSetAttribute(k_main, cudaFuncAttributeMaxDynamicSharedMemorySize, SMEM_BYTES);
    k_main<<<Nn / BI, TPB, SMEM_BYTES>>>(geo, sem, out);
}